// round 7
// baseline (speedup 1.0000x reference)
#include <cuda_runtime.h>
#include <cstdint>

// PANNAcceptor: out[b] = lin_w @ (W[x_{L-1}] ... W[x_0] e0) + lin_b
// Round 7: PLANAR fp24 weights.
//   hi-plane: uint16 per element (bytes 3,2 of fp32 word)
//   lo-plane: uint8  per element (extra mantissa byte)
//   decode  : ONE PRMT per element builds [L, L, Hlo, Hhi]; the quantizer
//             rounds onto the lattice H*65536 + L*257, so the duplicated
//             low byte is exact -- no mask, no bias, fp24-grade error
//             (measured 2.3e-4 total in R6, gate is 1e-3).
//   loads   : per row-lane 1x LDG.128 (hi) + 1x LDG.64 (lo), both perfectly
//             coalesced -> 128 B/wavefront (R6's interleaved layout got 42).
// Structure = R1 (best): 1 CTA/batch, 512 thr, h ping-pong in smem.

#define NST  256
#define TPB  512          // 16 warps, 16 rows each
#define MAXA 128

__device__ unsigned short g_hi[(size_t)MAXA * NST * NST];   // 16.8 MB @128
__device__ unsigned char  g_lo[(size_t)MAXA * NST * NST];   //  8.4 MB

// ---------------- quantize: fp32 -> planar fp24 lattice ----------------
// element value decoded as bits (H<<16) | (L<<8) | L  ==  H*65536 + L*257.
// Nearest-lattice rounding: H = u>>16, L = round((u&0xFFFF)/257).
__global__ void pann_quant(const float* __restrict__ W, int total4)
{
    for (int i = blockIdx.x * blockDim.x + threadIdx.x; i < total4;
         i += gridDim.x * blockDim.x) {
        const float4 f = ((const float4*)W)[i];
        uint32_t u0 = __float_as_uint(f.x), u1 = __float_as_uint(f.y);
        uint32_t u2 = __float_as_uint(f.z), u3 = __float_as_uint(f.w);
        // L = round(t/257) via (t*255 + 32768) >> 16  (exact enough: |err|<0.005)
        uint32_t l0 = ((u0 & 0xFFFFu) * 255u + 32768u) >> 16;
        uint32_t l1 = ((u1 & 0xFFFFu) * 255u + 32768u) >> 16;
        uint32_t l2 = ((u2 & 0xFFFFu) * 255u + 32768u) >> 16;
        uint32_t l3 = ((u3 & 0xFFFFu) * 255u + 32768u) >> 16;
        ushort4 h;
        h.x = (unsigned short)(u0 >> 16);
        h.y = (unsigned short)(u1 >> 16);
        h.z = (unsigned short)(u2 >> 16);
        h.w = (unsigned short)(u3 >> 16);
        ((ushort4*)g_hi)[i] = h;
        ((uint32_t*)g_lo)[i] = l0 | (l1 << 8) | (l2 << 16) | (l3 << 24);
    }
}

// decode: bytes [L, L, Hlo, Hhi]
__device__ __forceinline__ float pf(uint32_t hw, uint32_t lw, uint32_t sel) {
    return __uint_as_float(__byte_perm(hw, lw, sel));
}

__device__ __forceinline__ float warp_reduce16(float v) {
    v += __shfl_xor_sync(0xffffffffu, v, 8);
    v += __shfl_xor_sync(0xffffffffu, v, 4);
    v += __shfl_xor_sync(0xffffffffu, v, 2);
    v += __shfl_xor_sync(0xffffffffu, v, 1);
    return v;
}

// dot of 8 planar-fp24 cols against 8 h values
__device__ __forceinline__ float row_dot(const uint4 H, const uint2 Lw,
                                         const float4 h0, const float4 h1)
{
    // H.x = [H0lo,H0hi,H1lo,H1hi], Lw.x = [L0,L1,L2,L3], etc.
    const float e0 = pf(H.x, Lw.x, 0x1044u);
    const float e1 = pf(H.x, Lw.x, 0x3255u);
    const float e2 = pf(H.y, Lw.x, 0x1066u);
    const float e3 = pf(H.y, Lw.x, 0x3277u);
    const float e4 = pf(H.z, Lw.y, 0x1044u);
    const float e5 = pf(H.z, Lw.y, 0x3255u);
    const float e6 = pf(H.w, Lw.y, 0x1066u);
    const float e7 = pf(H.w, Lw.y, 0x3277u);
    return e0*h0.x + e1*h0.y + e2*h0.z + e3*h0.w
         + e4*h1.x + e5*h1.y + e6*h1.z + e7*h1.w;
}

// ---------------- main chain kernel (planar fp24) ----------------
__global__ __launch_bounds__(TPB, 1)
void pann_chain24p(const int* __restrict__ xs,
                   const int* __restrict__ lengths,
                   const float* __restrict__ lin_w,
                   const float* __restrict__ lin_b,
                   float* __restrict__ out,
                   int S)
{
    __shared__ float hbuf[2][NST];

    const int b    = blockIdx.x;
    const int tid  = threadIdx.x;
    const int warp = tid >> 5;
    const int lane = tid & 31;

    if (tid < NST) hbuf[0][tid] = (tid == 0) ? 1.0f : 0.0f;

    const int L = lengths[b];
    const int* xrow = xs + (size_t)b * S;
    __syncthreads();

    int cur = 0;
    const int i0 = warp * 16;   // this warp's 16 rows
    int a = __ldg(xrow);

    for (int t = 0; t < L; ++t) {
        const int a_cur = a;
        if (t + 1 < L) a = __ldg(xrow + t + 1);   // prefetch next symbol

        const unsigned char* hib =
            (const unsigned char*)g_hi + (size_t)a_cur * (NST * NST * 2)
            + (size_t)i0 * (NST * 2) + lane * 16;
        const unsigned char* lob =
            g_lo + (size_t)a_cur * (NST * NST)
            + (size_t)i0 * NST + lane * 8;

        const float* hsrc = hbuf[cur];
        float* hdst = hbuf[cur ^ 1];

        // lane's h slice: cols [8l, 8l+8)
        const float4 h0 = ((const float4*)hsrc)[2 * lane];
        const float4 h1 = ((const float4*)hsrc)[2 * lane + 1];

        #pragma unroll 4
        for (int j = 0; j < 16; j += 2) {
            const uint4 Ha = *(const uint4*)(hib + (size_t)j * (NST * 2));
            const uint2 La = *(const uint2*)(lob + (size_t)j * NST);
            const uint4 Hb = *(const uint4*)(hib + (size_t)(j + 1) * (NST * 2));
            const uint2 Lb = *(const uint2*)(lob + (size_t)(j + 1) * NST);

            float sA = row_dot(Ha, La, h0, h1);
            float sB = row_dot(Hb, Lb, h0, h1);

            // fold: lanes<16 reduce row j, lanes>=16 reduce row j+1
            const float oA = __shfl_xor_sync(0xffffffffu, sA, 16);
            const float oB = __shfl_xor_sync(0xffffffffu, sB, 16);
            float v = (lane < 16) ? (sA + oA) : (sB + oB);
            v = warp_reduce16(v);
            if (lane == 0)  hdst[i0 + j]     = v;
            if (lane == 16) hdst[i0 + j + 1] = v;
        }
        __syncthreads();
        cur ^= 1;
    }

    // linear head
    const float* hf = hbuf[L & 1];
    if (warp < 2) {
        float s = 0.0f;
        #pragma unroll
        for (int i = lane; i < NST; i += 32)
            s += lin_w[warp * NST + i] * hf[i];
        s += __shfl_xor_sync(0xffffffffu, s, 16);
        s = warp_reduce16(s);
        if (lane == 0) out[b * 2 + warp] = s + lin_b[warp];
    }
}

// ---------------- fallback (R1, full fp32) for unexpected shapes ------------
__global__ __launch_bounds__(512, 1)
void pann_chain_fp32(const int* __restrict__ xs,
                     const int* __restrict__ lengths,
                     const float* __restrict__ W,
                     const float* __restrict__ lin_w,
                     const float* __restrict__ lin_b,
                     float* __restrict__ out,
                     int S)
{
    __shared__ float hbuf[2][NST];
    const int b = blockIdx.x, tid = threadIdx.x, warp = tid >> 5, lane = tid & 31;
    if (tid < NST) hbuf[0][tid] = (tid == 0) ? 1.0f : 0.0f;
    const int L = lengths[b];
    const int* xrow = xs + (size_t)b * S;
    __syncthreads();
    int cur = 0;
    const int i0 = warp * 16;
    for (int t = 0; t < L; ++t) {
        const int a = __ldg(xrow + t);
        const float* Wa = W + (size_t)a * (NST * NST);
        const float* hsrc = hbuf[cur];
        float* hdst = hbuf[cur ^ 1];
        const float4 hA = ((const float4*)hsrc)[lane];
        const float4 hB = ((const float4*)hsrc)[32 + lane];
        #pragma unroll 4
        for (int r = 0; r < 16; ++r) {
            const int i = i0 + r;
            const float4* p = (const float4*)(Wa + (size_t)i * NST + lane * 4);
            const float4 wA = p[0];
            const float4 wB = p[32];
            float s = wA.x*hA.x + wA.y*hA.y + wA.z*hA.z + wA.w*hA.w
                    + wB.x*hB.x + wB.y*hB.y + wB.z*hB.z + wB.w*hB.w;
            s += __shfl_xor_sync(0xffffffffu, s, 16);
            s = warp_reduce16(s);
            if (lane == 0) hdst[i] = s;
        }
        __syncthreads();
        cur ^= 1;
    }
    const float* hf = hbuf[cur];
    if (warp < 2) {
        float s = 0.0f;
        #pragma unroll
        for (int i = lane; i < NST; i += 32) s += lin_w[warp * NST + i] * hf[i];
        s += __shfl_xor_sync(0xffffffffu, s, 16);
        s = warp_reduce16(s);
        if (lane == 0) out[b * 2 + warp] = s + lin_b[warp];
    }
}

extern "C" void kernel_launch(void* const* d_in, const int* in_sizes, int n_in,
                              void* d_out, int out_size)
{
    const int*   xs      = (const int*)d_in[0];
    const int*   lengths = (const int*)d_in[1];
    const float* W       = (const float*)d_in[2];
    const float* lin_w   = (const float*)d_in[3];
    const float* lin_b   = (const float*)d_in[4];
    float*       out     = (float*)d_out;

    const int B = in_sizes[1];
    const int S = in_sizes[0] / B;
    const int A = in_sizes[2] / (NST * NST);

    if (A >= 1 && A <= MAXA) {
        const int total4 = in_sizes[2] / 4;
        pann_quant<<<2048, 256>>>(W, total4);
        pann_chain24p<<<B, TPB>>>(xs, lengths, lin_w, lin_b, out, S);
    } else {
        pann_chain_fp32<<<B, 512>>>(xs, lengths, W, lin_w, lin_b, out, S);
    }
}

// round 8
// speedup vs baseline: 1.3973x; 1.3973x over previous
#include <cuda_runtime.h>
#include <cstdint>

// PANNAcceptor: out[b] = lin_w @ (W[x_{L-1}] ... W[x_0] e0) + lin_b
// Round 8: forward/backward mid-split + LPT work scheduling.
//   Every chain with L>=16 is split at M=L/2:
//     forward item : h <- W[x_t] h        over t in [0,M)      (R1 loop)
//     backward item: v <- v W[x_t]        over t in [L-1..M]   (same loop on W^T)
//   out = v . h_M + lin_b. Halves max sequential depth (1016 -> ~508) with
//   ZERO extra W traffic. Items sorted by descending steps (LPT) device-side.
//   W^T built once per replay (~15us). All CTAs independent (no clusters).

#define NST  256
#define TPB  512
#define MAXA 128
#define MAXB 128
#define SPLIT_MIN 16

__device__ float g_WT[(size_t)MAXA * NST * NST];     // W transposed
__device__ float g_hmid[MAXB][NST];
__device__ int   g_flag[MAXB];
__device__ int4  g_items[2 * MAXB];                  // {b, start, count, dir}

// dir: 0 = forward partial (write h_mid), 1 = backward, 2 = forward whole

// ---------------- sync helpers ----------------
__device__ __forceinline__ int ld_acq(const int* p) {
    int v; asm volatile("ld.acquire.gpu.global.s32 %0, [%1];" : "=r"(v) : "l"(p) : "memory");
    return v;
}
__device__ __forceinline__ void st_rel(int* p, int v) {
    asm volatile("st.release.gpu.global.s32 [%0], %1;" :: "l"(p), "r"(v) : "memory");
}
__device__ __forceinline__ float ld_cv(const float* p) {
    float v; asm volatile("ld.volatile.global.f32 %0, [%1];" : "=f"(v) : "l"(p) : "memory");
    return v;
}
__device__ __forceinline__ float warp_reduce16(float v) {
    v += __shfl_xor_sync(0xffffffffu, v, 8);
    v += __shfl_xor_sync(0xffffffffu, v, 4);
    v += __shfl_xor_sync(0xffffffffu, v, 2);
    v += __shfl_xor_sync(0xffffffffu, v, 1);
    return v;
}

// ---------------- W transpose (per replay; ~26MB) ----------------
__global__ void pann_transpose(const float* __restrict__ W)
{
    __shared__ float tile[32][33];
    const int a  = blockIdx.z;
    const int jt = blockIdx.y * 32;      // row tile in W
    const int ct = blockIdx.x * 32;      // col tile in W
    const float* Wa = W + (size_t)a * NST * NST;
    float* Ta = g_WT + (size_t)a * NST * NST;
    const int tx = threadIdx.x, ty = threadIdx.y;
    #pragma unroll
    for (int k = 0; k < 4; ++k)
        tile[ty + 8 * k][tx] = Wa[(size_t)(jt + ty + 8 * k) * NST + ct + tx];
    __syncthreads();
    #pragma unroll
    for (int k = 0; k < 4; ++k)
        Ta[(size_t)(ct + ty + 8 * k) * NST + jt + tx] = tile[tx][ty + 8 * k];
}

// ---------------- scheduler: build + LPT-sort items, reset flags ------------
__global__ void pann_sched(const int* __restrict__ lengths, int B)
{
    __shared__ int4 tmp[2 * MAXB];
    __shared__ int  cnt[2 * MAXB];
    const int tid = threadIdx.x;           // 256 threads

    if (tid < B) {
        const int L = lengths[tid];
        if (L >= SPLIT_MIN) {
            const int M = L >> 1;
            tmp[2 * tid]     = make_int4(tid, 0, M, 0);       // forward partial
            tmp[2 * tid + 1] = make_int4(tid, M, L - M, 1);   // backward
        } else {
            tmp[2 * tid]     = make_int4(tid, 0, L, 2);       // forward whole
            tmp[2 * tid + 1] = make_int4(tid, 0, 0, 3);       // idle
        }
        g_flag[tid] = 0;
    }
    const int n = 2 * B;
    if (tid < n) cnt[tid] = tmp[tid].z;
    __syncthreads();

    if (tid < n) {
        const int c = cnt[tid];
        int r = 0;
        for (int s = 0; s < n; ++s) {
            const int c2 = cnt[s];
            r += (c2 > c) || (c2 == c && s < tid);
        }
        g_items[r] = tmp[tid];
    } else {
        g_items[tid] = make_int4(0, 0, 0, 3);                 // idle padding
    }
}

// ---------------- main kernel ----------------
__global__ __launch_bounds__(TPB)
void pann_main(const int* __restrict__ xs,
               const float* __restrict__ W,
               const float* __restrict__ lin_w,
               const float* __restrict__ lin_b,
               float* __restrict__ out,
               int S)
{
    __shared__ float hbuf[2][NST];        // forward h ping-pong
    __shared__ float vbuf[2][2][NST];     // backward v ping-pong (2 rows)

    const int4 it = g_items[blockIdx.x];
    const int count = it.z;
    if (count <= 0) return;
    const int b = it.x, start = it.y, dir = it.w;

    const int tid  = threadIdx.x;
    const int warp = tid >> 5;
    const int lane = tid & 31;
    const int* xrow = xs + (size_t)b * S;

    if (dir != 1) {
        // ================= FORWARD (R1 loop) =================
        if (tid < NST) hbuf[0][tid] = (tid == 0) ? 1.0f : 0.0f;
        __syncthreads();

        int cur = 0;
        const int i0 = warp * 16;
        int a = __ldg(xrow);

        for (int t = 0; t < count; ++t) {
            const int a_cur = a;
            if (t + 1 < count) a = __ldg(xrow + t + 1);

            const float* Wa = W + (size_t)a_cur * (NST * NST);
            const float* hsrc = hbuf[cur];
            float* hdst = hbuf[cur ^ 1];

            const float4 hA = ((const float4*)hsrc)[lane];
            const float4 hB = ((const float4*)hsrc)[32 + lane];

            #pragma unroll 4
            for (int r = 0; r < 16; ++r) {
                const int i = i0 + r;
                const float4* p = (const float4*)(Wa + (size_t)i * NST + lane * 4);
                const float4 wA = p[0];
                const float4 wB = p[32];
                float s = wA.x*hA.x + wA.y*hA.y + wA.z*hA.z + wA.w*hA.w
                        + wB.x*hB.x + wB.y*hB.y + wB.z*hB.z + wB.w*hB.w;
                s += __shfl_xor_sync(0xffffffffu, s, 16);
                s = warp_reduce16(s);
                if (lane == 0) hdst[i] = s;
            }
            __syncthreads();
            cur ^= 1;
        }

        const float* hf = hbuf[count & 1];
        if (dir == 2) {
            // whole chain: emit output directly
            if (warp < 2) {
                float s = 0.0f;
                #pragma unroll
                for (int i = lane; i < NST; i += 32)
                    s += lin_w[warp * NST + i] * hf[i];
                s += __shfl_xor_sync(0xffffffffu, s, 16);
                s = warp_reduce16(s);
                if (lane == 0) out[b * 2 + warp] = s + lin_b[warp];
            }
        } else {
            // partial: publish h_mid, release flag
            if (tid < NST / 4)
                ((float4*)g_hmid[b])[tid] = ((const float4*)hf)[tid];
            __syncthreads();
            if (tid == 0) { __threadfence(); st_rel(&g_flag[b], 1); }
        }
        return;
    }

    // ================= BACKWARD (same loop shape on W^T) =================
    // v (2 x 256) seeded with lin_w; v_new[k][c] = sum_j WT[c][j] * v[k][j]
    if (tid < NST) {
        vbuf[0][0][tid] = lin_w[tid];
        vbuf[0][1][tid] = lin_w[NST + tid];
    }
    __syncthreads();

    int cur = 0;
    const int c0 = warp * 16;              // this warp's 16 output columns
    int a = __ldg(xrow + (start + count - 1));

    for (int s = count - 1; s >= 0; --s) {
        const int a_cur = a;
        if (s > 0) a = __ldg(xrow + start + s - 1);

        const float* Ta = g_WT + (size_t)a_cur * (NST * NST);
        const float* v0 = vbuf[cur][0];
        const float* v1 = vbuf[cur][1];
        float* d0 = vbuf[cur ^ 1][0];
        float* d1 = vbuf[cur ^ 1][1];

        const float4 v0a = ((const float4*)v0)[lane];
        const float4 v0b = ((const float4*)v0)[32 + lane];
        const float4 v1a = ((const float4*)v1)[lane];
        const float4 v1b = ((const float4*)v1)[32 + lane];

        #pragma unroll 4
        for (int j = 0; j < 16; ++j) {
            const int c = c0 + j;
            const float4* p = (const float4*)(Ta + (size_t)c * NST + lane * 4);
            const float4 wA = p[0];          // contiguous 512B per warp
            const float4 wB = p[32];
            // same weights, two accumulators (k = 0,1)
            float sA = wA.x*v0a.x + wA.y*v0a.y + wA.z*v0a.z + wA.w*v0a.w
                     + wB.x*v0b.x + wB.y*v0b.y + wB.z*v0b.z + wB.w*v0b.w;
            float sB = wA.x*v1a.x + wA.y*v1a.y + wA.z*v1a.z + wA.w*v1a.w
                     + wB.x*v1b.x + wB.y*v1b.y + wB.z*v1b.z + wB.w*v1b.w;
            // fold: lanes<16 reduce k=0, lanes>=16 reduce k=1
            const float oA = __shfl_xor_sync(0xffffffffu, sA, 16);
            const float oB = __shfl_xor_sync(0xffffffffu, sB, 16);
            float v = (lane < 16) ? (sA + oA) : (sB + oB);
            v = warp_reduce16(v);
            if (lane == 0)  d0[c] = v;
            if (lane == 16) d1[c] = v;
        }
        __syncthreads();
        cur ^= 1;
    }

    // wait for forward half, then combine: out[b][k] = v[k] . h_mid + lin_b[k]
    if (tid == 0) { while (ld_acq(&g_flag[b]) == 0) { } }
    __syncthreads();

    if (warp < 2) {
        const float* vf = vbuf[count & 1][warp];
        const float* hm = g_hmid[b];
        float s = 0.0f;
        #pragma unroll
        for (int i = lane; i < NST; i += 32)
            s += vf[i] * ld_cv(hm + i);
        s += __shfl_xor_sync(0xffffffffu, s, 16);
        s = warp_reduce16(s);
        if (lane == 0) out[b * 2 + warp] = s + lin_b[warp];
    }
}

// ---------------- fallback (R1) for unexpected shapes ----------------
__global__ __launch_bounds__(512, 1)
void pann_chain_fp32(const int* __restrict__ xs,
                     const int* __restrict__ lengths,
                     const float* __restrict__ W,
                     const float* __restrict__ lin_w,
                     const float* __restrict__ lin_b,
                     float* __restrict__ out,
                     int S)
{
    __shared__ float hbuf[2][NST];
    const int b = blockIdx.x, tid = threadIdx.x, warp = tid >> 5, lane = tid & 31;
    if (tid < NST) hbuf[0][tid] = (tid == 0) ? 1.0f : 0.0f;
    const int L = lengths[b];
    const int* xrow = xs + (size_t)b * S;
    __syncthreads();
    int cur = 0;
    const int i0 = warp * 16;
    for (int t = 0; t < L; ++t) {
        const int a = __ldg(xrow + t);
        const float* Wa = W + (size_t)a * (NST * NST);
        const float* hsrc = hbuf[cur];
        float* hdst = hbuf[cur ^ 1];
        const float4 hA = ((const float4*)hsrc)[lane];
        const float4 hB = ((const float4*)hsrc)[32 + lane];
        #pragma unroll 4
        for (int r = 0; r < 16; ++r) {
            const int i = i0 + r;
            const float4* p = (const float4*)(Wa + (size_t)i * NST + lane * 4);
            const float4 wA = p[0];
            const float4 wB = p[32];
            float s = wA.x*hA.x + wA.y*hA.y + wA.z*hA.z + wA.w*hA.w
                    + wB.x*hB.x + wB.y*hB.y + wB.z*hB.z + wB.w*hB.w;
            s += __shfl_xor_sync(0xffffffffu, s, 16);
            s = warp_reduce16(s);
            if (lane == 0) hdst[i] = s;
        }
        __syncthreads();
        cur ^= 1;
    }
    const float* hf = hbuf[cur];
    if (warp < 2) {
        float s = 0.0f;
        #pragma unroll
        for (int i = lane; i < NST; i += 32) s += lin_w[warp * NST + i] * hf[i];
        s += __shfl_xor_sync(0xffffffffu, s, 16);
        s = warp_reduce16(s);
        if (lane == 0) out[b * 2 + warp] = s + lin_b[warp];
    }
}

extern "C" void kernel_launch(void* const* d_in, const int* in_sizes, int n_in,
                              void* d_out, int out_size)
{
    const int*   xs      = (const int*)d_in[0];
    const int*   lengths = (const int*)d_in[1];
    const float* W       = (const float*)d_in[2];
    const float* lin_w   = (const float*)d_in[3];
    const float* lin_b   = (const float*)d_in[4];
    float*       out     = (float*)d_out;

    const int B = in_sizes[1];
    const int S = in_sizes[0] / B;
    const int A = in_sizes[2] / (NST * NST);

    if (A >= 1 && A <= MAXA && B >= 1 && B <= MAXB) {
        dim3 tgrid(NST / 32, NST / 32, A);
        pann_transpose<<<tgrid, dim3(32, 8)>>>(W);
        pann_sched<<<1, 2 * MAXB>>>(lengths, B);
        pann_main<<<2 * B, TPB>>>(xs, W, lin_w, lin_b, out, S);
    } else {
        pann_chain_fp32<<<B, 512>>>(xs, lengths, W, lin_w, lin_b, out, S);
    }
}

// round 9
// speedup vs baseline: 1.8359x; 1.3138x over previous
#include <cuda_runtime.h>
#include <cstdint>

// PANNAcceptor: out[b] = lin_w @ (W[x_{L-1}] ... W[x_0] e0) + lin_b
// Round 9: planar fp24 weights + FRONT-BATCHED loads in the exact R1 shape.
//   - R1 structure is proven to sit at the per-SM L1-ingest floor
//     (2048 cy/step for 256 KB). fp24 cuts that to 192 KB -> 1536 cy floor
//     and cuts chip L2 traffic 25%.
//   - R7 lost because loads serialized (MLP~2). Here each warp processes its
//     16 rows as two 8-row groups, loading ALL 16 vectors (8x LDG.128 hi +
//     8x LDG.64 lo) into register arrays BEFORE any decode -> MLP ~16.
//   - decode: 1 PRMT/element builds [L, L, Hlo, Hhi]; quantizer rounds onto
//     the lattice H*65536 + L*257 so the duplicated byte is exact.
//     Accumulated rel_err measured 1.7e-4 (R7) vs 1e-3 gate.
//   - ~76 regs/thread also enforces 1 CTA/SM (the co-residency loss from
//     R5/R8 cannot recur).

#define NST  256
#define TPB  512          // 16 warps, 16 rows each
#define MAXA 128

__device__ unsigned short g_hi[(size_t)MAXA * NST * NST];   // top 2 bytes
__device__ unsigned char  g_lo[(size_t)MAXA * NST * NST];   // 3rd byte

// ---------------- quantize: fp32 -> planar fp24 lattice ----------------
// decoded bits = (H<<16) | (L<<8) | L = H*65536 + L*257
__global__ void pann_quant(const float* __restrict__ W, int total4)
{
    for (int i = blockIdx.x * blockDim.x + threadIdx.x; i < total4;
         i += gridDim.x * blockDim.x) {
        const float4 f = ((const float4*)W)[i];
        uint32_t u0 = __float_as_uint(f.x), u1 = __float_as_uint(f.y);
        uint32_t u2 = __float_as_uint(f.z), u3 = __float_as_uint(f.w);
        uint32_t l0 = ((u0 & 0xFFFFu) * 255u + 32768u) >> 16;
        uint32_t l1 = ((u1 & 0xFFFFu) * 255u + 32768u) >> 16;
        uint32_t l2 = ((u2 & 0xFFFFu) * 255u + 32768u) >> 16;
        uint32_t l3 = ((u3 & 0xFFFFu) * 255u + 32768u) >> 16;
        ushort4 h;
        h.x = (unsigned short)(u0 >> 16);
        h.y = (unsigned short)(u1 >> 16);
        h.z = (unsigned short)(u2 >> 16);
        h.w = (unsigned short)(u3 >> 16);
        ((ushort4*)g_hi)[i] = h;
        ((uint32_t*)g_lo)[i] = l0 | (l1 << 8) | (l2 << 16) | (l3 << 24);
    }
}

__device__ __forceinline__ float pf(uint32_t hw, uint32_t lw, uint32_t sel) {
    return __uint_as_float(__byte_perm(hw, lw, sel));
}
__device__ __forceinline__ float warp_reduce16(float v) {
    v += __shfl_xor_sync(0xffffffffu, v, 8);
    v += __shfl_xor_sync(0xffffffffu, v, 4);
    v += __shfl_xor_sync(0xffffffffu, v, 2);
    v += __shfl_xor_sync(0xffffffffu, v, 1);
    return v;
}

// dot of 8 planar-fp24 cols against 8 h values (all data already in regs)
__device__ __forceinline__ float row_dot(const uint4 H, const uint2 Lw,
                                         const float4 h0, const float4 h1)
{
    const float e0 = pf(H.x, Lw.x, 0x1044u);
    const float e1 = pf(H.x, Lw.x, 0x3255u);
    const float e2 = pf(H.y, Lw.x, 0x1066u);
    const float e3 = pf(H.y, Lw.x, 0x3277u);
    const float e4 = pf(H.z, Lw.y, 0x1044u);
    const float e5 = pf(H.z, Lw.y, 0x3255u);
    const float e6 = pf(H.w, Lw.y, 0x1066u);
    const float e7 = pf(H.w, Lw.y, 0x3277u);
    return e0*h0.x + e1*h0.y + e2*h0.z + e3*h0.w
         + e4*h1.x + e5*h1.y + e6*h1.z + e7*h1.w;
}

// ---------------- main chain kernel ----------------
__global__ __launch_bounds__(TPB, 1)
void pann_chain24g(const int* __restrict__ xs,
                   const int* __restrict__ lengths,
                   const float* __restrict__ lin_w,
                   const float* __restrict__ lin_b,
                   float* __restrict__ out,
                   int S)
{
    __shared__ float hbuf[2][NST];

    const int b    = blockIdx.x;
    const int tid  = threadIdx.x;
    const int warp = tid >> 5;
    const int lane = tid & 31;

    if (tid < NST) hbuf[0][tid] = (tid == 0) ? 1.0f : 0.0f;

    const int L = lengths[b];
    const int* xrow = xs + (size_t)b * S;
    __syncthreads();

    int cur = 0;
    const int i0 = warp * 16;            // this warp's 16 rows
    int a = __ldg(xrow);

    for (int t = 0; t < L; ++t) {
        const int a_cur = a;
        if (t + 1 < L) a = __ldg(xrow + t + 1);   // prefetch next symbol

        const unsigned char* hib =
            (const unsigned char*)g_hi + ((size_t)a_cur * NST + i0) * (NST * 2)
            + lane * 16;
        const unsigned char* lob =
            g_lo + ((size_t)a_cur * NST + i0) * NST + lane * 8;

        const float* hsrc = hbuf[cur];
        float* hdst = hbuf[cur ^ 1];

        // lane's h slice: cols [8l, 8l+8)
        const float4 h0 = ((const float4*)hsrc)[2 * lane];
        const float4 h1 = ((const float4*)hsrc)[2 * lane + 1];

        #pragma unroll
        for (int g = 0; g < 2; ++g) {
            const unsigned char* hg = hib + (size_t)(g * 8) * (NST * 2);
            const unsigned char* lg = lob + (size_t)(g * 8) * NST;

            // ---- front-batched load phase: 16 independent LDGs ----
            uint4 H[8];
            uint2 Lo[8];
            #pragma unroll
            for (int r = 0; r < 8; ++r)
                H[r] = *(const uint4*)(hg + (size_t)r * (NST * 2));
            #pragma unroll
            for (int r = 0; r < 8; ++r)
                Lo[r] = *(const uint2*)(lg + (size_t)r * NST);

            // ---- compute phase ----
            #pragma unroll
            for (int r = 0; r < 8; r += 2) {
                float sA = row_dot(H[r],     Lo[r],     h0, h1);
                float sB = row_dot(H[r + 1], Lo[r + 1], h0, h1);

                // fold: lanes<16 reduce row r, lanes>=16 reduce row r+1
                const float oA = __shfl_xor_sync(0xffffffffu, sA, 16);
                const float oB = __shfl_xor_sync(0xffffffffu, sB, 16);
                float v = (lane < 16) ? (sA + oA) : (sB + oB);
                v = warp_reduce16(v);
                const int i = i0 + g * 8 + r;
                if (lane == 0)  hdst[i]     = v;
                if (lane == 16) hdst[i + 1] = v;
            }
        }
        __syncthreads();
        cur ^= 1;
    }

    // linear head
    const float* hf = hbuf[L & 1];
    if (warp < 2) {
        float s = 0.0f;
        #pragma unroll
        for (int i = lane; i < NST; i += 32)
            s += lin_w[warp * NST + i] * hf[i];
        s += __shfl_xor_sync(0xffffffffu, s, 16);
        s = warp_reduce16(s);
        if (lane == 0) out[b * 2 + warp] = s + lin_b[warp];
    }
}

// ---------------- fallback (R1, full fp32) for unexpected shapes ------------
__global__ __launch_bounds__(512, 1)
void pann_chain_fp32(const int* __restrict__ xs,
                     const int* __restrict__ lengths,
                     const float* __restrict__ W,
                     const float* __restrict__ lin_w,
                     const float* __restrict__ lin_b,
                     float* __restrict__ out,
                     int S)
{
    __shared__ float hbuf[2][NST];
    const int b = blockIdx.x, tid = threadIdx.x, warp = tid >> 5, lane = tid & 31;
    if (tid < NST) hbuf[0][tid] = (tid == 0) ? 1.0f : 0.0f;
    const int L = lengths[b];
    const int* xrow = xs + (size_t)b * S;
    __syncthreads();
    int cur = 0;
    const int i0 = warp * 16;
    for (int t = 0; t < L; ++t) {
        const int a = __ldg(xrow + t);
        const float* Wa = W + (size_t)a * (NST * NST);
        const float* hsrc = hbuf[cur];
        float* hdst = hbuf[cur ^ 1];
        const float4 hA = ((const float4*)hsrc)[lane];
        const float4 hB = ((const float4*)hsrc)[32 + lane];
        #pragma unroll 4
        for (int r = 0; r < 16; ++r) {
            const int i = i0 + r;
            const float4* p = (const float4*)(Wa + (size_t)i * NST + lane * 4);
            const float4 wA = p[0];
            const float4 wB = p[32];
            float s = wA.x*hA.x + wA.y*hA.y + wA.z*hA.z + wA.w*hA.w
                    + wB.x*hB.x + wB.y*hB.y + wB.z*hB.z + wB.w*hB.w;
            s += __shfl_xor_sync(0xffffffffu, s, 16);
            s = warp_reduce16(s);
            if (lane == 0) hdst[i] = s;
        }
        __syncthreads();
        cur ^= 1;
    }
    const float* hf = hbuf[cur];
    if (warp < 2) {
        float s = 0.0f;
        #pragma unroll
        for (int i = lane; i < NST; i += 32) s += lin_w[warp * NST + i] * hf[i];
        s += __shfl_xor_sync(0xffffffffu, s, 16);
        s = warp_reduce16(s);
        if (lane == 0) out[b * 2 + warp] = s + lin_b[warp];
    }
}

extern "C" void kernel_launch(void* const* d_in, const int* in_sizes, int n_in,
                              void* d_out, int out_size)
{
    const int*   xs      = (const int*)d_in[0];
    const int*   lengths = (const int*)d_in[1];
    const float* W       = (const float*)d_in[2];
    const float* lin_w   = (const float*)d_in[3];
    const float* lin_b   = (const float*)d_in[4];
    float*       out     = (float*)d_out;

    const int B = in_sizes[1];
    const int S = in_sizes[0] / B;
    const int A = in_sizes[2] / (NST * NST);

    if (A >= 1 && A <= MAXA) {
        const int total4 = in_sizes[2] / 4;
        pann_quant<<<2048, 256>>>(W, total4);
        pann_chain24g<<<B, TPB>>>(xs, lengths, lin_w, lin_b, out, S);
    } else {
        pann_chain_fp32<<<B, 512>>>(xs, lengths, W, lin_w, lin_b, out, S);
    }
}

// round 10
// speedup vs baseline: 2.1630x; 1.1782x over previous
#include <cuda_runtime.h>
#include <cstdint>

// PANNAcceptor: out[b] = lin_w @ (W[x_{L-1}] ... W[x_0] e0) + lin_b
// Round 10: LPT scheduling over the proven R1 inner loop.
//   Chip L2 cap supports ~47 full-rate chains; running all 128 CTAs at once
//   (R1) processor-shares everyone down to ~0.37 steps/us and the longest
//   chain finishes ~0.9ms late. Instead: K=64 persistent CTAs pop chains
//   from a queue sorted by DESCENDING length (classic LPT) -> the straggler
//   runs at near-solo rate from t=0 and the makespan approaches
//   max(total/C, L_max/r) ~= 1.4-1.5ms.
//   Inner loop, precision, layout: identical to R1 (fp32, 2048cy/step floor).

#define NST  256
#define TPB  512          // 16 warps, 16 rows each
#define MAXB 1024
#define KCTA 64

__device__ int g_order[MAXB];
__device__ int g_next;

// ---------------- scheduler: rank batches by (L desc, idx), reset queue -----
__global__ void pann_sched(const int* __restrict__ lengths, int B)
{
    const int tid = threadIdx.x;
    if (tid == 0) g_next = 0;
    if (tid < B) {
        const int L = lengths[tid];
        int rank = 0;
        for (int s = 0; s < B; ++s) {
            const int L2 = lengths[s];
            rank += (L2 > L) || (L2 == L && s < tid);
        }
        g_order[rank] = tid;
    }
}

__device__ __forceinline__ float warp_reduce16(float v) {
    v += __shfl_xor_sync(0xffffffffu, v, 8);
    v += __shfl_xor_sync(0xffffffffu, v, 4);
    v += __shfl_xor_sync(0xffffffffu, v, 2);
    v += __shfl_xor_sync(0xffffffffu, v, 1);
    return v;
}

// ---------------- persistent LPT worker ----------------
__global__ __launch_bounds__(TPB, 1)
void pann_lpt(const int* __restrict__ xs,
              const int* __restrict__ lengths,
              const float* __restrict__ W,
              const float* __restrict__ lin_w,
              const float* __restrict__ lin_b,
              float* __restrict__ out,
              int S, int B)
{
    __shared__ float hbuf[2][NST];
    __shared__ int s_b;

    const int tid  = threadIdx.x;
    const int warp = tid >> 5;
    const int lane = tid & 31;
    const int i0 = warp * 16;            // this warp's 16 rows

    for (;;) {
        if (tid == 0) {
            const int idx = atomicAdd(&g_next, 1);
            s_b = (idx < B) ? g_order[idx] : -1;
        }
        __syncthreads();                 // publishes s_b; fences prior hbuf use
        const int b = s_b;
        if (b < 0) return;

        // ---- R1 chain loop for batch b ----
        if (tid < NST) hbuf[0][tid] = (tid == 0) ? 1.0f : 0.0f;

        const int L = lengths[b];
        const int* xrow = xs + (size_t)b * S;
        __syncthreads();

        int cur = 0;
        int a = __ldg(xrow);

        for (int t = 0; t < L; ++t) {
            const int a_cur = a;
            if (t + 1 < L) a = __ldg(xrow + t + 1);   // prefetch next symbol

            const float* Wa = W + (size_t)a_cur * (NST * NST);
            const float* hsrc = hbuf[cur];
            float* hdst = hbuf[cur ^ 1];

            const float4 hA = ((const float4*)hsrc)[lane];
            const float4 hB = ((const float4*)hsrc)[32 + lane];

            #pragma unroll 4
            for (int r = 0; r < 16; ++r) {
                const int i = i0 + r;
                const float4* p = (const float4*)(Wa + (size_t)i * NST + lane * 4);
                const float4 wA = p[0];     // cols [4l,4l+4)      512B/warp contiguous
                const float4 wB = p[32];    // cols [128+4l,+4)
                float s = wA.x*hA.x + wA.y*hA.y + wA.z*hA.z + wA.w*hA.w
                        + wB.x*hB.x + wB.y*hB.y + wB.z*hB.z + wB.w*hB.w;
                s += __shfl_xor_sync(0xffffffffu, s, 16);
                s = warp_reduce16(s);
                if (lane == 0) hdst[i] = s;
            }
            __syncthreads();
            cur ^= 1;
        }

        // ---- linear head ----
        const float* hf = hbuf[L & 1];
        if (warp < 2) {
            float s = 0.0f;
            #pragma unroll
            for (int i = lane; i < NST; i += 32)
                s += lin_w[warp * NST + i] * hf[i];
            s += __shfl_xor_sync(0xffffffffu, s, 16);
            s = warp_reduce16(s);
            if (lane == 0) out[b * 2 + warp] = s + lin_b[warp];
        }
        // loop back: __syncthreads at top protects hbuf/s_b reuse
    }
}

// ---------------- fallback (plain R1) for unexpected shapes ----------------
__global__ __launch_bounds__(512, 1)
void pann_chain_fp32(const int* __restrict__ xs,
                     const int* __restrict__ lengths,
                     const float* __restrict__ W,
                     const float* __restrict__ lin_w,
                     const float* __restrict__ lin_b,
                     float* __restrict__ out,
                     int S)
{
    __shared__ float hbuf[2][NST];
    const int b = blockIdx.x, tid = threadIdx.x, warp = tid >> 5, lane = tid & 31;
    if (tid < NST) hbuf[0][tid] = (tid == 0) ? 1.0f : 0.0f;
    const int L = lengths[b];
    const int* xrow = xs + (size_t)b * S;
    __syncthreads();
    int cur = 0;
    const int i0 = warp * 16;
    for (int t = 0; t < L; ++t) {
        const int a = __ldg(xrow + t);
        const float* Wa = W + (size_t)a * (NST * NST);
        const float* hsrc = hbuf[cur];
        float* hdst = hbuf[cur ^ 1];
        const float4 hA = ((const float4*)hsrc)[lane];
        const float4 hB = ((const float4*)hsrc)[32 + lane];
        #pragma unroll 4
        for (int r = 0; r < 16; ++r) {
            const int i = i0 + r;
            const float4* p = (const float4*)(Wa + (size_t)i * NST + lane * 4);
            const float4 wA = p[0];
            const float4 wB = p[32];
            float s = wA.x*hA.x + wA.y*hA.y + wA.z*hA.z + wA.w*hA.w
                    + wB.x*hB.x + wB.y*hB.y + wB.z*hB.z + wB.w*hB.w;
            s += __shfl_xor_sync(0xffffffffu, s, 16);
            s = warp_reduce16(s);
            if (lane == 0) hdst[i] = s;
        }
        __syncthreads();
        cur ^= 1;
    }
    const float* hf = hbuf[cur];
    if (warp < 2) {
        float s = 0.0f;
        #pragma unroll
        for (int i = lane; i < NST; i += 32) s += lin_w[warp * NST + i] * hf[i];
        s += __shfl_xor_sync(0xffffffffu, s, 16);
        s = warp_reduce16(s);
        if (lane == 0) out[b * 2 + warp] = s + lin_b[warp];
    }
}

extern "C" void kernel_launch(void* const* d_in, const int* in_sizes, int n_in,
                              void* d_out, int out_size)
{
    const int*   xs      = (const int*)d_in[0];
    const int*   lengths = (const int*)d_in[1];
    const float* W       = (const float*)d_in[2];
    const float* lin_w   = (const float*)d_in[3];
    const float* lin_b   = (const float*)d_in[4];
    float*       out     = (float*)d_out;

    const int B = in_sizes[1];
    const int S = in_sizes[0] / B;

    if (B >= 1 && B <= MAXB) {
        const int sthreads = (B + 31) / 32 * 32;
        pann_sched<<<1, sthreads < 32 ? 32 : sthreads>>>(lengths, B);
        const int K = (B < KCTA) ? B : KCTA;
        pann_lpt<<<K, TPB>>>(xs, lengths, W, lin_w, lin_b, out, S, B);
    } else {
        pann_chain_fp32<<<B, 512>>>(xs, lengths, W, lin_w, lin_b, out, S);
    }
}

// round 11
// speedup vs baseline: 2.2429x; 1.0369x over previous
#include <cuda_runtime.h>
#include <cstdint>

// PANNAcceptor: out[b] = lin_w @ (W[x_{L-1}] ... W[x_0] e0) + lin_b
// Round 11: fp24 weights in the EXACT R1 codegen shape + LPT scheduling.
//   Measured fact: chip L2->L1 cap for this pattern is ~7.5 TB/s; fp32
//   streaming sits on its 2.29ms floor (R1=2311, R10-LPT=2292). Only fewer
//   bytes can go lower. fp24 (validated rel_err 1.7e-4 vs 1e-3 gate) cuts
//   traffic 25% -> 1.76ms floor.
//   Past fp24 attempts lost to codegen (loads stopped batching). Fix: pack
//   each row as [512B hi(uint16) | 256B lo(uint8)] contiguous, 768B stride.
//   Per row: 2 loads at immediate offsets from 2 base regs -- the same
//   structure R1's p[0]/p[32] pattern that ptxas batches to MLP~8.
//   decode: 1 PRMT/element builds [L,L,Hlo,Hhi]; quantizer rounds onto the
//   lattice H*65536 + L*257 so the duplicated byte is exact.

#define NST  256
#define TPB  512          // 16 warps, 16 rows each
#define MAXA 128
#define MAXB 1024
#define KCTA 96
#define ROWB 768          // bytes per packed row: 512 hi + 256 lo

__device__ unsigned char g_w24[(size_t)MAXA * NST * ROWB];   // 25.2 MB @128
__device__ int g_order[MAXB];
__device__ int g_next;

// ---------------- quantize: fp32 -> packed planar fp24 ----------------
// decoded bits = (H<<16) | (L<<8) | L = H*65536 + L*257 (nearest lattice pt)
__global__ void pann_quant(const float* __restrict__ W, int total4)
{
    for (int i = blockIdx.x * blockDim.x + threadIdx.x; i < total4;
         i += gridDim.x * blockDim.x) {
        const float4 f = ((const float4*)W)[i];
        uint32_t u0 = __float_as_uint(f.x), u1 = __float_as_uint(f.y);
        uint32_t u2 = __float_as_uint(f.z), u3 = __float_as_uint(f.w);
        uint32_t l0 = ((u0 & 0xFFFFu) * 255u + 32768u) >> 16;
        uint32_t l1 = ((u1 & 0xFFFFu) * 255u + 32768u) >> 16;
        uint32_t l2 = ((u2 & 0xFFFFu) * 255u + 32768u) >> 16;
        uint32_t l3 = ((u3 & 0xFFFFu) * 255u + 32768u) >> 16;
        ushort4 h;
        h.x = (unsigned short)(u0 >> 16);
        h.y = (unsigned short)(u1 >> 16);
        h.z = (unsigned short)(u2 >> 16);
        h.w = (unsigned short)(u3 >> 16);

        const int col4 = i & 63;            // 64 float4 per row
        const int row  = i >> 6;            // global row index (a*256 + r)
        unsigned char* rb = g_w24 + (size_t)row * ROWB;
        *(ushort4*)(rb + col4 * 8) = h;                       // hi plane
        *(uint32_t*)(rb + 512 + col4 * 4) =
            l0 | (l1 << 8) | (l2 << 16) | (l3 << 24);         // lo plane
    }
}

// ---------------- scheduler: rank batches by (L desc, idx) ----------------
__global__ void pann_sched(const int* __restrict__ lengths, int B)
{
    const int tid = threadIdx.x;
    if (tid == 0) g_next = 0;
    if (tid < B) {
        const int L = lengths[tid];
        int rank = 0;
        for (int s = 0; s < B; ++s) {
            const int L2 = lengths[s];
            rank += (L2 > L) || (L2 == L && s < tid);
        }
        g_order[rank] = tid;
    }
}

__device__ __forceinline__ float pf(uint32_t hw, uint32_t lw, uint32_t sel) {
    return __uint_as_float(__byte_perm(hw, lw, sel));
}
__device__ __forceinline__ float warp_reduce16(float v) {
    v += __shfl_xor_sync(0xffffffffu, v, 8);
    v += __shfl_xor_sync(0xffffffffu, v, 4);
    v += __shfl_xor_sync(0xffffffffu, v, 2);
    v += __shfl_xor_sync(0xffffffffu, v, 1);
    return v;
}

// ---------------- persistent LPT worker (fp24) ----------------
__global__ __launch_bounds__(TPB, 1)
void pann_lpt24(const int* __restrict__ xs,
                const int* __restrict__ lengths,
                const float* __restrict__ lin_w,
                const float* __restrict__ lin_b,
                float* __restrict__ out,
                int S, int B)
{
    __shared__ float hbuf[2][NST];
    __shared__ int s_b;

    const int tid  = threadIdx.x;
    const int warp = tid >> 5;
    const int lane = tid & 31;
    const int i0 = warp * 16;            // this warp's 16 rows

    for (;;) {
        if (tid == 0) {
            const int idx = atomicAdd(&g_next, 1);
            s_b = (idx < B) ? g_order[idx] : -1;
        }
        __syncthreads();
        const int b = s_b;
        if (b < 0) return;

        if (tid < NST) hbuf[0][tid] = (tid == 0) ? 1.0f : 0.0f;

        const int L = lengths[b];
        const int* xrow = xs + (size_t)b * S;
        __syncthreads();

        int cur = 0;
        int a = __ldg(xrow);

        for (int t = 0; t < L; ++t) {
            const int a_cur = a;
            if (t + 1 < L) a = __ldg(xrow + t + 1);   // prefetch next symbol

            // two base pointers for this warp's row block; per-row offsets
            // are compile-time immediates (r*768 and r*768) -> ptxas batches.
            const unsigned char* basew =
                g_w24 + (size_t)(a_cur * NST + i0) * ROWB;
            const unsigned char* ph = basew + lane * 16;         // hi slice
            const unsigned char* pl = basew + 512 + lane * 8;    // lo slice

            const float* hsrc = hbuf[cur];
            float* hdst = hbuf[cur ^ 1];

            // lane's h slice: cols [8l, 8l+8)
            const float4 h0 = ((const float4*)hsrc)[2 * lane];
            const float4 h1 = ((const float4*)hsrc)[2 * lane + 1];

            #pragma unroll 4
            for (int r = 0; r < 16; ++r) {
                const uint4 H  = *(const uint4*)(ph + r * ROWB);
                const uint2 Lw = *(const uint2*)(pl + r * ROWB);

                const float e0 = pf(H.x, Lw.x, 0x1044u);
                const float e1 = pf(H.x, Lw.x, 0x3255u);
                const float e2 = pf(H.y, Lw.x, 0x1066u);
                const float e3 = pf(H.y, Lw.x, 0x3277u);
                const float e4 = pf(H.z, Lw.y, 0x1044u);
                const float e5 = pf(H.z, Lw.y, 0x3255u);
                const float e6 = pf(H.w, Lw.y, 0x1066u);
                const float e7 = pf(H.w, Lw.y, 0x3277u);

                float s = e0*h0.x + e1*h0.y + e2*h0.z + e3*h0.w
                        + e4*h1.x + e5*h1.y + e6*h1.z + e7*h1.w;

                s += __shfl_xor_sync(0xffffffffu, s, 16);
                s = warp_reduce16(s);
                if (lane == 0) hdst[i0 + r] = s;
            }
            __syncthreads();
            cur ^= 1;
        }

        // ---- linear head ----
        const float* hf = hbuf[L & 1];
        if (warp < 2) {
            float s = 0.0f;
            #pragma unroll
            for (int i = lane; i < NST; i += 32)
                s += lin_w[warp * NST + i] * hf[i];
            s += __shfl_xor_sync(0xffffffffu, s, 16);
            s = warp_reduce16(s);
            if (lane == 0) out[b * 2 + warp] = s + lin_b[warp];
        }
    }
}

// ---------------- fallback (plain R1) for unexpected shapes ----------------
__global__ __launch_bounds__(512, 1)
void pann_chain_fp32(const int* __restrict__ xs,
                     const int* __restrict__ lengths,
                     const float* __restrict__ W,
                     const float* __restrict__ lin_w,
                     const float* __restrict__ lin_b,
                     float* __restrict__ out,
                     int S)
{
    __shared__ float hbuf[2][NST];
    const int b = blockIdx.x, tid = threadIdx.x, warp = tid >> 5, lane = tid & 31;
    if (tid < NST) hbuf[0][tid] = (tid == 0) ? 1.0f : 0.0f;
    const int L = lengths[b];
    const int* xrow = xs + (size_t)b * S;
    __syncthreads();
    int cur = 0;
    const int i0 = warp * 16;
    for (int t = 0; t < L; ++t) {
        const int a = __ldg(xrow + t);
        const float* Wa = W + (size_t)a * (NST * NST);
        const float* hsrc = hbuf[cur];
        float* hdst = hbuf[cur ^ 1];
        const float4 hA = ((const float4*)hsrc)[lane];
        const float4 hB = ((const float4*)hsrc)[32 + lane];
        #pragma unroll 4
        for (int r = 0; r < 16; ++r) {
            const int i = i0 + r;
            const float4* p = (const float4*)(Wa + (size_t)i * NST + lane * 4);
            const float4 wA = p[0];
            const float4 wB = p[32];
            float s = wA.x*hA.x + wA.y*hA.y + wA.z*hA.z + wA.w*hA.w
                    + wB.x*hB.x + wB.y*hB.y + wB.z*hB.z + wB.w*hB.w;
            s += __shfl_xor_sync(0xffffffffu, s, 16);
            s = warp_reduce16(s);
            if (lane == 0) hdst[i] = s;
        }
        __syncthreads();
        cur ^= 1;
    }
    const float* hf = hbuf[cur];
    if (warp < 2) {
        float s = 0.0f;
        #pragma unroll
        for (int i = lane; i < NST; i += 32) s += lin_w[warp * NST + i] * hf[i];
        s += __shfl_xor_sync(0xffffffffu, s, 16);
        s = warp_reduce16(s);
        if (lane == 0) out[b * 2 + warp] = s + lin_b[warp];
    }
}

extern "C" void kernel_launch(void* const* d_in, const int* in_sizes, int n_in,
                              void* d_out, int out_size)
{
    const int*   xs      = (const int*)d_in[0];
    const int*   lengths = (const int*)d_in[1];
    const float* W       = (const float*)d_in[2];
    const float* lin_w   = (const float*)d_in[3];
    const float* lin_b   = (const float*)d_in[4];
    float*       out     = (float*)d_out;

    const int B = in_sizes[1];
    const int S = in_sizes[0] / B;
    const int A = in_sizes[2] / (NST * NST);

    if (A >= 1 && A <= MAXA && B >= 1 && B <= MAXB) {
        const int total4 = in_sizes[2] / 4;
        pann_quant<<<2048, 256>>>(W, total4);
        const int sthreads = ((B + 31) / 32 * 32) < 32 ? 32 : ((B + 31) / 32 * 32);
        pann_sched<<<1, sthreads>>>(lengths, B);
        const int K = (B < KCTA) ? B : KCTA;
        pann_lpt24<<<K, TPB>>>(xs, lengths, lin_w, lin_b, out, S, B);
    } else {
        pann_chain_fp32<<<B, 512>>>(xs, lengths, W, lin_w, lin_b, out, S);
    }
}